// round 1
// baseline (speedup 1.0000x reference)
#include <cuda_runtime.h>
#include <cuda_bf16.h>
#include <math.h>

#define F 128
#define NMAX 50000
#define ROWS 16   // rows per epilogue tile

// scratch for hi = A @ x  (25.6 MB, static device array: no allocations allowed)
__device__ float g_hi[(size_t)NMAX * F];

// ---------------------------------------------------------------------------
// Kernel 1: zero the hi accumulator (float4 stores)
// ---------------------------------------------------------------------------
__global__ void zero_hi_kernel(int n_float4) {
    int i = blockIdx.x * blockDim.x + threadIdx.x;
    if (i < n_float4) {
        ((float4*)g_hi)[i] = make_float4(0.f, 0.f, 0.f, 0.f);
    }
}

// ---------------------------------------------------------------------------
// Kernel 2: edge scatter. One warp per edge: 32 lanes x float4 = 128 floats.
// Gather x[src] (coalesced 512B), vector-reduce into g_hi[dst].
// ---------------------------------------------------------------------------
__global__ void scatter_kernel(const float* __restrict__ x,
                               const float* __restrict__ edge_w,
                               const int* __restrict__ edge_src,
                               const int* __restrict__ edge_dst,
                               int E) {
    int gtid = blockIdx.x * blockDim.x + threadIdx.x;
    int warp = gtid >> 5;
    int lane = gtid & 31;
    if (warp >= E) return;

    int s = edge_src[warp];
    int d = edge_dst[warp];
    float w = edge_w[warp];

    const float4* xs = (const float4*)(x + (size_t)s * F);
    float4 v = xs[lane];
    float* p = g_hi + (size_t)d * F + lane * 4;

    asm volatile(
        "red.global.add.v4.f32 [%0], {%1, %2, %3, %4};"
        :: "l"(p), "f"(v.x * w), "f"(v.y * w), "f"(v.z * w), "f"(v.w * w)
        : "memory");
}

// ---------------------------------------------------------------------------
// Kernel 3: fused epilogue.
//   theta = log(lamda/l + 1);  W' = theta*W + (1-theta)*I
//   S = (1-alpha)*hi + alpha*h0
//   out = S @ W' + x
// blockDim = 128 (thread j owns output column j). Persistent-grid over
// 16-row tiles. W' (64KB) + S tile (8KB) in dynamic smem.
// ---------------------------------------------------------------------------
__global__ void epilogue_kernel(const float* __restrict__ h0,
                                const float* __restrict__ x,
                                const float* __restrict__ weight,
                                const float* __restrict__ lamda_p,
                                const float* __restrict__ alpha_p,
                                const int* __restrict__ l_p,
                                float* __restrict__ out,
                                int Nn) {
    extern __shared__ float sh[];          // [0, 16384): W', [16384, +ROWS*128): S tile
    float* Wp = sh;
    float* stile = sh + F * F;

    int tid = threadIdx.x;                 // 0..127 = output column j

    float lamda = lamda_p[0];
    float alpha = alpha_p[0];
    float lf = (float)l_p[0];
    float theta = logf(lamda / lf + 1.0f);
    float one_m_theta = 1.0f - theta;
    float one_m_alpha = 1.0f - alpha;

    // Build W' in smem: W'[k][j] = theta*W[k][j] + (k==j ? 1-theta : 0)
    for (int i = tid; i < F * F; i += blockDim.x) {
        int k = i >> 7;
        int j = i & 127;
        float v = theta * weight[i];
        if (k == j) v += one_m_theta;
        Wp[i] = v;
    }
    __syncthreads();

    int ntiles = (Nn + ROWS - 1) / ROWS;
    for (int tile = blockIdx.x; tile < ntiles; tile += gridDim.x) {
        int row0 = tile * ROWS;
        int nr = min(ROWS, Nn - row0);

        // Load S tile: stile[r][j] = (1-alpha)*hi + alpha*h0  (coalesced)
        for (int r = 0; r < nr; r++) {
            size_t idx = (size_t)(row0 + r) * F + tid;
            stile[r * F + tid] = one_m_alpha * g_hi[idx] + alpha * h0[idx];
        }
        __syncthreads();

        float acc[ROWS];
        #pragma unroll
        for (int r = 0; r < ROWS; r++) acc[r] = 0.0f;

        #pragma unroll
        for (int k = 0; k < F; k += 4) {
            float w0 = Wp[(k + 0) * F + tid];
            float w1 = Wp[(k + 1) * F + tid];
            float w2 = Wp[(k + 2) * F + tid];
            float w3 = Wp[(k + 3) * F + tid];
            #pragma unroll
            for (int r = 0; r < ROWS; r++) {
                float4 s4 = *(const float4*)&stile[r * F + k];
                acc[r] += s4.x * w0;
                acc[r] += s4.y * w1;
                acc[r] += s4.z * w2;
                acc[r] += s4.w * w3;
            }
        }

        for (int r = 0; r < nr; r++) {
            size_t idx = (size_t)(row0 + r) * F + tid;
            out[idx] = acc[r] + x[idx];
        }
        __syncthreads();   // protect stile before next tile overwrites it
    }
}

// ---------------------------------------------------------------------------
extern "C" void kernel_launch(void* const* d_in, const int* in_sizes, int n_in,
                              void* d_out, int out_size) {
    const float* x      = (const float*)d_in[0];
    const float* h0     = (const float*)d_in[1];
    const float* ew     = (const float*)d_in[2];
    const float* weight = (const float*)d_in[3];
    const float* lamda  = (const float*)d_in[4];
    const float* alpha  = (const float*)d_in[5];
    const int*   esrc   = (const int*)d_in[6];
    const int*   edst   = (const int*)d_in[7];
    const int*   lp     = (const int*)d_in[8];

    int Nn = in_sizes[0] / F;
    int E  = in_sizes[2];
    float* out = (float*)d_out;

    // 1) zero hi
    int n_f4 = Nn * (F / 4);
    zero_hi_kernel<<<(n_f4 + 255) / 256, 256>>>(n_f4);

    // 2) edge scatter (one warp per edge)
    long long threads = (long long)E * 32;
    int blocks = (int)((threads + 255) / 256);
    scatter_kernel<<<blocks, 256>>>(x, ew, esrc, edst, E);

    // 3) fused epilogue
    int smem_bytes = (F * F + ROWS * F) * (int)sizeof(float);   // 73728
    cudaFuncSetAttribute(epilogue_kernel,
                         cudaFuncAttributeMaxDynamicSharedMemorySize, smem_bytes);
    epilogue_kernel<<<444, F, smem_bytes>>>(h0, x, weight, lamda, alpha, lp, out, Nn);
}

// round 2
// speedup vs baseline: 1.2152x; 1.2152x over previous
#include <cuda_runtime.h>
#include <cuda_bf16.h>
#include <math.h>

#define F 128
#define NMAX 50000
#define ROWS 16     // rows per epilogue tile (50000 % 16 == 0)
#define CAP 64      // bucket capacity per destination row (P(deg>=64) ~ 0)

// static scratch (no allocations allowed)
__device__ float  g_hi[(size_t)NMAX * F];          // 25.6 MB
__device__ float2 g_slots[(size_t)NMAX * CAP];     // 25.6 MB  (src-as-bits, w)
__device__ int    g_cnt[NMAX];                     // 200 KB

// ---------------------------------------------------------------------------
// Kernel 1: zero hi accumulator + bucket counters
// ---------------------------------------------------------------------------
__global__ void zero_kernel(int n_float4, int Nn) {
    int i = blockIdx.x * blockDim.x + threadIdx.x;
    if (i < n_float4)
        ((float4*)g_hi)[i] = make_float4(0.f, 0.f, 0.f, 0.f);
    if (i < Nn)
        g_cnt[i] = 0;
}

// ---------------------------------------------------------------------------
// Kernel 2: bucket fill. One thread per edge: claim a slot in dst's bucket,
// write (src, w). Overflow (~never) falls back to direct atomic scatter.
// ---------------------------------------------------------------------------
__global__ void fill_kernel(const float* __restrict__ x,
                            const float* __restrict__ edge_w,
                            const int* __restrict__ edge_src,
                            const int* __restrict__ edge_dst,
                            int E) {
    int e = blockIdx.x * blockDim.x + threadIdx.x;
    if (e >= E) return;
    int d = edge_dst[e];
    int s = edge_src[e];
    float w = edge_w[e];
    int pos = atomicAdd(&g_cnt[d], 1);
    if (pos < CAP) {
        g_slots[(size_t)d * CAP + pos] = make_float2(__int_as_float(s), w);
    } else {
        // correctness fallback: scatter this edge directly into g_hi
        const float4* xs = (const float4*)(x + (size_t)s * F);
        float* p = g_hi + (size_t)d * F;
        for (int i = 0; i < F / 4; i++) {
            float4 v = xs[i];
            asm volatile("red.global.add.v4.f32 [%0], {%1, %2, %3, %4};"
                :: "l"(p + i * 4), "f"(v.x * w), "f"(v.y * w),
                   "f"(v.z * w), "f"(v.w * w) : "memory");
        }
    }
}

// ---------------------------------------------------------------------------
// Kernel 3: gather. One warp per destination row. Each lane owns a float4
// chunk of the 128-wide feature vector. Edges broadcast via shfl.
// Adds into g_hi with red.v4 (coexists with the overflow fallback path).
// ---------------------------------------------------------------------------
__global__ void gather_kernel(const float* __restrict__ x, int Nn) {
    int gtid = blockIdx.x * blockDim.x + threadIdx.x;
    int row = gtid >> 5;
    int lane = gtid & 31;
    if (row >= Nn) return;

    int cnt = g_cnt[row];
    if (cnt > CAP) cnt = CAP;

    float4 acc = make_float4(0.f, 0.f, 0.f, 0.f);
    const float2* slotp = g_slots + (size_t)row * CAP;

    for (int base = 0; base < cnt; base += 32) {
        int m = min(32, cnt - base);
        float2 myslot = (lane < m) ? slotp[base + lane] : make_float2(0.f, 0.f);
        int ms = __float_as_int(myslot.x);
        #pragma unroll 4
        for (int e = 0; e < m; e++) {
            int   s  = __shfl_sync(0xffffffffu, ms, e);
            float wt = __shfl_sync(0xffffffffu, myslot.y, e);
            float4 v = ((const float4*)(x + (size_t)s * F))[lane];
            acc.x += wt * v.x;
            acc.y += wt * v.y;
            acc.z += wt * v.z;
            acc.w += wt * v.w;
        }
    }

    float* p = g_hi + (size_t)row * F + lane * 4;
    asm volatile("red.global.add.v4.f32 [%0], {%1, %2, %3, %4};"
        :: "l"(p), "f"(acc.x), "f"(acc.y), "f"(acc.z), "f"(acc.w) : "memory");
}

// ---------------------------------------------------------------------------
// Kernel 4: fused epilogue with packed f32x2 FMA.
//   theta = log(lamda/l + 1);  W' = theta*W + (1-theta)*I
//   S = (1-alpha)*hi + alpha*h0 ;  out = S @ W' + x
// 128 threads (thread = output column). 16-row tiles, rows processed in
// packed pairs via fma.rn.f32x2 (2x fp32 FMA throughput on sm_103a).
// ---------------------------------------------------------------------------
#define PACK2(dst, lo, hi) \
    asm("mov.b64 %0, {%1, %2};" : "=l"(dst) : "f"(lo), "f"(hi))
#define FMA2(acc, a, b) \
    asm("fma.rn.f32x2 %0, %1, %2, %0;" : "+l"(acc) : "l"(a), "l"(b))

__global__ void epilogue_kernel(const float* __restrict__ h0,
                                const float* __restrict__ x,
                                const float* __restrict__ weight,
                                const float* __restrict__ lamda_p,
                                const float* __restrict__ alpha_p,
                                const int* __restrict__ l_p,
                                float* __restrict__ out,
                                int Nn) {
    extern __shared__ float sh[];          // W' (64KB) then S tile (8KB)
    float* Wp = sh;
    float* stile = sh + F * F;

    int tid = threadIdx.x;                 // output column j

    float lamda = lamda_p[0];
    float alpha = alpha_p[0];
    float lf = (float)l_p[0];
    float theta = logf(lamda / lf + 1.0f);
    float one_m_theta = 1.0f - theta;
    float one_m_alpha = 1.0f - alpha;

    // W'[k][j] = theta*W[k][j] + (k==j ? 1-theta : 0)
    for (int i = tid; i < F * F; i += blockDim.x) {
        int k = i >> 7;
        int j = i & 127;
        float v = theta * weight[i];
        if (k == j) v += one_m_theta;
        Wp[i] = v;
    }
    __syncthreads();

    int ntiles = (Nn + ROWS - 1) / ROWS;
    for (int tile = blockIdx.x; tile < ntiles; tile += gridDim.x) {
        int row0 = tile * ROWS;
        int nr = min(ROWS, Nn - row0);

        // S tile (coalesced per row); zero-fill tail rows
        for (int r = 0; r < nr; r++) {
            size_t idx = (size_t)(row0 + r) * F + tid;
            stile[r * F + tid] = one_m_alpha * g_hi[idx] + alpha * h0[idx];
        }
        for (int r = nr; r < ROWS; r++) stile[r * F + tid] = 0.f;
        __syncthreads();

        unsigned long long acc[ROWS / 2];
        #pragma unroll
        for (int rp = 0; rp < ROWS / 2; rp++) acc[rp] = 0ull;

        #pragma unroll
        for (int k = 0; k < F; k += 4) {
            float w0 = Wp[(k + 0) * F + tid];
            float w1 = Wp[(k + 1) * F + tid];
            float w2 = Wp[(k + 2) * F + tid];
            float w3 = Wp[(k + 3) * F + tid];
            unsigned long long wd0, wd1, wd2, wd3;
            PACK2(wd0, w0, w0);
            PACK2(wd1, w1, w1);
            PACK2(wd2, w2, w2);
            PACK2(wd3, w3, w3);
            #pragma unroll
            for (int rp = 0; rp < ROWS / 2; rp++) {
                float4 a = *(const float4*)&stile[(2 * rp) * F + k];
                float4 b = *(const float4*)&stile[(2 * rp + 1) * F + k];
                unsigned long long p;
                PACK2(p, a.x, b.x); FMA2(acc[rp], p, wd0);
                PACK2(p, a.y, b.y); FMA2(acc[rp], p, wd1);
                PACK2(p, a.z, b.z); FMA2(acc[rp], p, wd2);
                PACK2(p, a.w, b.w); FMA2(acc[rp], p, wd3);
            }
        }

        #pragma unroll
        for (int rp = 0; rp < ROWS / 2; rp++) {
            float lo, hi;
            asm("mov.b64 {%0, %1}, %2;" : "=f"(lo), "=f"(hi) : "l"(acc[rp]));
            int r0 = 2 * rp, r1 = 2 * rp + 1;
            if (r0 < nr) {
                size_t idx = (size_t)(row0 + r0) * F + tid;
                out[idx] = lo + x[idx];
            }
            if (r1 < nr) {
                size_t idx = (size_t)(row0 + r1) * F + tid;
                out[idx] = hi + x[idx];
            }
        }
        __syncthreads();   // protect stile before next tile
    }
}

// ---------------------------------------------------------------------------
extern "C" void kernel_launch(void* const* d_in, const int* in_sizes, int n_in,
                              void* d_out, int out_size) {
    const float* x      = (const float*)d_in[0];
    const float* h0     = (const float*)d_in[1];
    const float* ew     = (const float*)d_in[2];
    const float* weight = (const float*)d_in[3];
    const float* lamda  = (const float*)d_in[4];
    const float* alpha  = (const float*)d_in[5];
    const int*   esrc   = (const int*)d_in[6];
    const int*   edst   = (const int*)d_in[7];
    const int*   lp     = (const int*)d_in[8];

    int Nn = in_sizes[0] / F;
    int E  = in_sizes[2];
    float* out = (float*)d_out;

    // 1) zero hi + counters
    int n_f4 = Nn * (F / 4);
    zero_kernel<<<(n_f4 + 255) / 256, 256>>>(n_f4, Nn);

    // 2) bucket fill
    fill_kernel<<<(E + 255) / 256, 256>>>(x, ew, esrc, edst, E);

    // 3) gather (one warp per row)
    long long gthreads = (long long)Nn * 32;
    gather_kernel<<<(int)((gthreads + 255) / 256), 256>>>(x, Nn);

    // 4) fused epilogue
    int smem_bytes = (F * F + ROWS * F) * (int)sizeof(float);   // 73728
    cudaFuncSetAttribute(epilogue_kernel,
                         cudaFuncAttributeMaxDynamicSharedMemorySize, smem_bytes);
    epilogue_kernel<<<444, F, smem_bytes>>>(h0, x, weight, lamda, alpha, lp, out, Nn);
}

// round 3
// speedup vs baseline: 1.8533x; 1.5251x over previous
#include <cuda_runtime.h>
#include <cuda_bf16.h>
#include <math.h>

#define F 128
#define NMAX 50000
#define EMAX 800000
#define CAP 64      // bucket capacity per destination row (P(deg>=64) ~ 0)
#define MT 64       // rows per epilogue tile

// static scratch (no allocations allowed)
__device__ float  g_S[(size_t)NMAX * F];           // S = (1-a)*A@x + a*h0, 25.6 MB
__device__ float2 g_slots[(size_t)NMAX * CAP];     // (src_bits, w) buckets, 25.6 MB
__device__ int    g_cnt[NMAX];
__device__ float4 g_over[EMAX];                    // overflow edges (src,dst,w,-)
__device__ int    g_overcnt;

// ---------------------------------------------------------------------------
// Kernel 1: zero bucket counters only (g_S is fully overwritten by gather)
// ---------------------------------------------------------------------------
__global__ void zero_cnt_kernel(int Nn) {
    int i = blockIdx.x * blockDim.x + threadIdx.x;
    if (i < Nn) g_cnt[i] = 0;
    if (i == 0) g_overcnt = 0;
}

// ---------------------------------------------------------------------------
// Kernel 2: bucket fill. One thread per edge. Overflow -> side list.
// ---------------------------------------------------------------------------
__global__ void fill_kernel(const float* __restrict__ edge_w,
                            const int* __restrict__ edge_src,
                            const int* __restrict__ edge_dst,
                            int E) {
    int e = blockIdx.x * blockDim.x + threadIdx.x;
    if (e >= E) return;
    int d = edge_dst[e];
    int s = edge_src[e];
    float w = edge_w[e];
    int pos = atomicAdd(&g_cnt[d], 1);
    if (pos < CAP) {
        g_slots[(size_t)d * CAP + pos] = make_float2(__int_as_float(s), w);
    } else {
        int o = atomicAdd(&g_overcnt, 1);
        if (o < EMAX)
            g_over[o] = make_float4(__int_as_float(s), __int_as_float(d), w, 0.f);
    }
}

// ---------------------------------------------------------------------------
// Kernel 3: gather + S fuse. One warp per row; lane owns a float4 chunk.
// Writes S[row] = (1-alpha) * sum_e w_e * x[src_e] + alpha * h0[row]  (plain STG)
// ---------------------------------------------------------------------------
__global__ void gather_kernel(const float* __restrict__ x,
                              const float* __restrict__ h0,
                              const float* __restrict__ alpha_p,
                              int Nn) {
    int gtid = blockIdx.x * blockDim.x + threadIdx.x;
    int row = gtid >> 5;
    int lane = gtid & 31;
    if (row >= Nn) return;

    float alpha = alpha_p[0];
    float oma = 1.0f - alpha;

    int cnt = g_cnt[row];
    if (cnt > CAP) cnt = CAP;

    float4 acc = make_float4(0.f, 0.f, 0.f, 0.f);
    const float2* slotp = g_slots + (size_t)row * CAP;

    for (int base = 0; base < cnt; base += 32) {
        int m = min(32, cnt - base);
        float2 myslot = (lane < m) ? slotp[base + lane] : make_float2(0.f, 0.f);
        int ms = __float_as_int(myslot.x);
        #pragma unroll 4
        for (int e = 0; e < m; e++) {
            int   s  = __shfl_sync(0xffffffffu, ms, e);
            float wt = __shfl_sync(0xffffffffu, myslot.y, e);
            float4 v = ((const float4*)(x + (size_t)s * F))[lane];
            acc.x += wt * v.x;
            acc.y += wt * v.y;
            acc.z += wt * v.z;
            acc.w += wt * v.w;
        }
    }

    float4 hv = ((const float4*)(h0 + (size_t)row * F))[lane];
    float4 S;
    S.x = oma * acc.x + alpha * hv.x;
    S.y = oma * acc.y + alpha * hv.y;
    S.z = oma * acc.z + alpha * hv.z;
    S.w = oma * acc.w + alpha * hv.w;
    ((float4*)(g_S + (size_t)row * F))[lane] = S;
}

// ---------------------------------------------------------------------------
// Kernel 4: drain overflow edges (normally zero). red.add into g_S.
// ---------------------------------------------------------------------------
__global__ void overflow_kernel(const float* __restrict__ x,
                                const float* __restrict__ alpha_p) {
    int n = g_overcnt;
    if (n > EMAX) n = EMAX;
    if (n == 0) return;
    float oma = 1.0f - alpha_p[0];
    long long total = (long long)n * 32;
    for (long long idx = blockIdx.x * blockDim.x + threadIdx.x;
         idx < total; idx += (long long)gridDim.x * blockDim.x) {
        int e = (int)(idx >> 5);
        int lane = (int)(idx & 31);
        float4 ov = g_over[e];
        int s = __float_as_int(ov.x);
        int d = __float_as_int(ov.y);
        float w = ov.z * oma;
        float4 v = ((const float4*)(x + (size_t)s * F))[lane];
        float* p = g_S + (size_t)d * F + lane * 4;
        asm volatile("red.global.add.v4.f32 [%0], {%1, %2, %3, %4};"
            :: "l"(p), "f"(w * v.x), "f"(w * v.y), "f"(w * v.z), "f"(w * v.w)
            : "memory");
    }
}

// ---------------------------------------------------------------------------
// Kernel 5: GEMM epilogue.  out = S @ W' + x,  W' = theta*W + (1-theta)*I
// 256 threads: thread = (cg = tid&31 -> cols 4cg..4cg+3, rg = tid>>5 -> rows
// 8rg..8rg+7). FFMA2 packs COLUMN pairs: w-pairs come free from LDS.128 of
// Wp (adjacent columns), only the broadcast s needs a dup (amortized x4).
// 16 independent accumulators per thread -> no RAW chains.
// ---------------------------------------------------------------------------
#define PACK2(dst, lo, hi) \
    asm("mov.b64 %0, {%1, %2};" : "=l"(dst) : "f"(lo), "f"(hi))
#define UNPACK2(lo, hi, src) \
    asm("mov.b64 {%0, %1}, %2;" : "=f"(lo), "=f"(hi) : "l"(src))
#define FMA2(acc, a, b) \
    asm("fma.rn.f32x2 %0, %1, %2, %0;" : "+l"(acc) : "l"(a), "l"(b))

__global__ void __launch_bounds__(256, 2)
epilogue_kernel(const float* __restrict__ x,
                const float* __restrict__ weight,
                const float* __restrict__ lamda_p,
                const int* __restrict__ l_p,
                float* __restrict__ out,
                int Nn) {
    extern __shared__ float sh[];
    float* Wp = sh;            // 128x128 = 64 KB
    float* st = sh + F * F;    // 64x128  = 32 KB

    int tid = threadIdx.x;
    int cg = tid & 31;         // column group: cols 4cg .. 4cg+3
    int rg = tid >> 5;         // row group (== warp id): rows 8rg .. 8rg+7

    float theta = logf(lamda_p[0] / (float)l_p[0] + 1.0f);
    float omt = 1.0f - theta;

    // W'[k][j] = theta*W[k][j] + (k==j ? 1-theta : 0)
    for (int i = tid; i < F * F; i += 256) {
        int k = i >> 7;
        int j = i & 127;
        float v = theta * weight[i];
        if (k == j) v += omt;
        Wp[i] = v;
    }
    __syncthreads();

    int ntiles = (Nn + MT - 1) / MT;
    for (int t = blockIdx.x; t < ntiles; t += gridDim.x) {
        int row0 = t * MT;

        // load S tile (coalesced float4), zero-pad tail rows
        for (int i = tid; i < MT * (F / 4); i += 256) {
            int r = i >> 5;
            int q = i & 31;
            float4 v = (row0 + r < Nn)
                ? ((const float4*)(g_S + (size_t)(row0 + r) * F))[q]
                : make_float4(0.f, 0.f, 0.f, 0.f);
            *(float4*)&st[r * F + q * 4] = v;
        }
        __syncthreads();

        unsigned long long acc[8][2];
        #pragma unroll
        for (int r = 0; r < 8; r++) { acc[r][0] = 0ull; acc[r][1] = 0ull; }

        for (int k = 0; k < F; k += 2) {
            float4 w0 = *(const float4*)&Wp[k * F + 4 * cg];
            float4 w1 = *(const float4*)&Wp[(k + 1) * F + 4 * cg];
            unsigned long long wp00, wp01, wp10, wp11;
            PACK2(wp00, w0.x, w0.y); PACK2(wp01, w0.z, w0.w);
            PACK2(wp10, w1.x, w1.y); PACK2(wp11, w1.z, w1.w);
            #pragma unroll
            for (int r = 0; r < 8; r++) {
                float2 s2 = *(const float2*)&st[(rg * 8 + r) * F + k]; // broadcast
                unsigned long long sp0, sp1;
                PACK2(sp0, s2.x, s2.x);
                PACK2(sp1, s2.y, s2.y);
                FMA2(acc[r][0], sp0, wp00);
                FMA2(acc[r][1], sp0, wp01);
                FMA2(acc[r][0], sp1, wp10);
                FMA2(acc[r][1], sp1, wp11);
            }
        }

        #pragma unroll
        for (int r = 0; r < 8; r++) {
            int row = row0 + rg * 8 + r;
            if (row < Nn) {
                float a0, a1, a2, a3;
                UNPACK2(a0, a1, acc[r][0]);
                UNPACK2(a2, a3, acc[r][1]);
                size_t base = (size_t)row * F + 4 * cg;
                float4 xv = *(const float4*)(x + base);
                float4 o = make_float4(a0 + xv.x, a1 + xv.y, a2 + xv.z, a3 + xv.w);
                *(float4*)(out + base) = o;
            }
        }
        __syncthreads();
    }
}

// ---------------------------------------------------------------------------
extern "C" void kernel_launch(void* const* d_in, const int* in_sizes, int n_in,
                              void* d_out, int out_size) {
    const float* x      = (const float*)d_in[0];
    const float* h0     = (const float*)d_in[1];
    const float* ew     = (const float*)d_in[2];
    const float* weight = (const float*)d_in[3];
    const float* lamda  = (const float*)d_in[4];
    const float* alpha  = (const float*)d_in[5];
    const int*   esrc   = (const int*)d_in[6];
    const int*   edst   = (const int*)d_in[7];
    const int*   lp     = (const int*)d_in[8];

    int Nn = in_sizes[0] / F;
    int E  = in_sizes[2];
    float* out = (float*)d_out;

    // 1) zero counters
    zero_cnt_kernel<<<(Nn + 255) / 256, 256>>>(Nn);

    // 2) bucket fill
    fill_kernel<<<(E + 255) / 256, 256>>>(ew, esrc, edst, E);

    // 3) gather + S fuse (one warp per row)
    long long gthreads = (long long)Nn * 32;
    gather_kernel<<<(int)((gthreads + 255) / 256), 256>>>(x, h0, alpha, Nn);

    // 4) drain overflow (normally no-op)
    overflow_kernel<<<64, 256>>>(x, alpha);

    // 5) GEMM epilogue
    int smem_bytes = (F * F + MT * F) * (int)sizeof(float);   // 98304
    cudaFuncSetAttribute(epilogue_kernel,
                         cudaFuncAttributeMaxDynamicSharedMemorySize, smem_bytes);
    epilogue_kernel<<<296, 256, smem_bytes>>>(x, weight, lamda, lp, out, Nn);
}